// round 6
// baseline (speedup 1.0000x reference)
#include <cuda_runtime.h>

// QConv2d: new_rho[b] = U2 @ rho[b] @ U2^T, U2 = uc[:,2:4] ⊗ ux ⊗ uy
// Fine-grained separable evaluation: NT=512, each thread owns 32 floats
// (4 runs of 8) per sub-pass. 2x the warps of the previous version.
//
// smem tile A: 128 rows x 132 floats (RS=132 -> per-phase conflict-free).
// Sub-passes:
//  P2a: gmem row-quarter -> regs, uy pass, store TRANSPOSED (col=cr*64+y*8+x)
//  P2b: load quarter (transposed), ux pass, store NORMAL (col=cr*64+x*8+y)
//  P3a: column c, rows [cl*64+xh*32,+32), uy-left pass (in own row set)
//  P3b: column c, stride-8 row groups, ux-left pass (in own row set)
//  P4 : fused uc on both sides + coalesced float4 stores (2 items/thread)

#define NT 512
#define RS 132
#define A_WORDS (128 * RS)          // 16896
#define SMEM_WORDS (A_WORDS + 136)
#define SMEM_BYTES (SMEM_WORDS * 4)

__device__ __forceinline__ float dot8(float4 ua, float4 ub, const float* v) {
    float a =      ua.x * v[0];
    a = fmaf(ua.y, v[1], a);
    a = fmaf(ua.z, v[2], a);
    a = fmaf(ua.w, v[3], a);
    a = fmaf(ub.x, v[4], a);
    a = fmaf(ub.y, v[5], a);
    a = fmaf(ub.z, v[6], a);
    a = fmaf(ub.w, v[7], a);
    return a;
}

__device__ __forceinline__ float dot8s4(float4 ua, float4 ub, const float* v) {
    // stride-4 dot: v[0],v[4],...,v[28]
    float a =      ua.x * v[0];
    a = fmaf(ua.y, v[4],  a);
    a = fmaf(ua.z, v[8],  a);
    a = fmaf(ua.w, v[12], a);
    a = fmaf(ub.x, v[16], a);
    a = fmaf(ub.y, v[20], a);
    a = fmaf(ub.z, v[24], a);
    a = fmaf(ub.w, v[28], a);
    return a;
}

__global__ __launch_bounds__(NT, 2)
void qconv_kernel(const float* __restrict__ rho,
                  const float* __restrict__ gux,
                  const float* __restrict__ guy,
                  const float* __restrict__ guc,
                  float* __restrict__ out)
{
    extern __shared__ float sm[];
    float* A  = sm;                 // 128 x 132
    float* sU = sm + A_WORDS;       // [0:64) uy, [64:128) ux, [128:136) wc

    const int tid = threadIdx.x;
    const int b   = blockIdx.x;

    // ---- init U + wc (tiny) ----
    if (tid < 64) {
        sU[tid] = guy[tid];
    } else if (tid < 128) {
        sU[tid] = gux[tid - 64];
    } else if (tid < 136) {
        const int i = tid - 128;                 // i = c'*2 + c
        sU[128 + i] = guc[(i >> 1) * 4 + (i & 1) + 2];
    }

    const int q  = tid >> 7;        // quarter 0..3
    const int r  = tid & 127;       // row (fast index -> good bank phases)
    const int cr = q >> 1;
    const int qh = q & 1;           // x-half for P2a, y-half for P2b

    // ---- P2a loads: row r, raw cols [q*32, q*32+32) from gmem ----
    float d[32];                    // d[xi*8 + y], x = qh*4 + xi
    {
        const float4* src = (const float4*)(rho + (long)b * 16384 + r * 128 + q * 32);
#pragma unroll
        for (int i = 0; i < 8; i++) {
            const float4 v = src[i];
            d[4 * i] = v.x; d[4 * i + 1] = v.y; d[4 * i + 2] = v.z; d[4 * i + 3] = v.w;
        }
    }
    __syncthreads();                // sU visible

    // ---- P2a: uy pass, store transposed (col = cr*64 + yo*8 + x) ----
    {
        float* Arow = A + r * RS + cr * 64 + qh * 4;
#pragma unroll
        for (int yo = 0; yo < 8; yo++) {
            const float4 ua = *(const float4*)(sU + yo * 8);
            const float4 ub = *(const float4*)(sU + yo * 8 + 4);
            float4 o;
            o.x = dot8(ua, ub, d);          // xi = 0
            o.y = dot8(ua, ub, d + 8);      // xi = 1
            o.z = dot8(ua, ub, d + 16);     // xi = 2
            o.w = dot8(ua, ub, d + 24);     // xi = 3
            *(float4*)(Arow + yo * 8) = o;
        }
    }
    __syncthreads();

    // ---- P2b: load quarter (transposed: d[yr*8 + x], y = qh*4 + yr) ----
    {
        const float* Arow = A + r * RS + q * 32;
#pragma unroll
        for (int i = 0; i < 8; i++) {
            const float4 v = *(const float4*)(Arow + 4 * i);
            d[4 * i] = v.x; d[4 * i + 1] = v.y; d[4 * i + 2] = v.z; d[4 * i + 3] = v.w;
        }
    }
    __syncthreads();                // all reads done before cross-thread writes

    // ux pass, store NORMAL layout (col = cr*64 + xo*8 + y), float4 over y
    {
        float* Arow = A + r * RS + cr * 64 + qh * 4;
#pragma unroll
        for (int xo = 0; xo < 8; xo++) {
            const float4 ua = *(const float4*)(sU + 64 + xo * 8);
            const float4 ub = *(const float4*)(sU + 64 + xo * 8 + 4);
            float4 o;
            o.x = dot8(ua, ub, d);          // yr = 0
            o.y = dot8(ua, ub, d + 8);      // yr = 1
            o.z = dot8(ua, ub, d + 16);     // yr = 2
            o.w = dot8(ua, ub, d + 24);     // yr = 3
            *(float4*)(Arow + xo * 8) = o;
        }
    }
    __syncthreads();

    // ---- P3a: uy-left. thread = (c, cl, xh): rows cl*64+xh*32+[0,32), col c ----
    {
        const int c  = tid & 127;
        const int cl = (tid >> 7) & 1;
        const int xh = tid >> 8;
        float* base = A + (cl * 64 + xh * 32) * RS + c;
#pragma unroll
        for (int i = 0; i < 32; i++) d[i] = base[i * RS];   // d[xr*8 + y]
#pragma unroll
        for (int yo = 0; yo < 8; yo++) {
            const float4 ua = *(const float4*)(sU + yo * 8);
            const float4 ub = *(const float4*)(sU + yo * 8 + 4);
            // out row = cl*64 + (xh*4+xr)*8 + yo  (within own row set)
            base[(0 * 8 + yo) * RS] = dot8(ua, ub, d);
            base[(1 * 8 + yo) * RS] = dot8(ua, ub, d + 8);
            base[(2 * 8 + yo) * RS] = dot8(ua, ub, d + 16);
            base[(3 * 8 + yo) * RS] = dot8(ua, ub, d + 24);
        }
    }
    __syncthreads();

    // ---- P3b: ux-left. thread = (c, cl, yh): rows cl*64 + x*8 + yh*4+yr ----
    {
        const int c  = tid & 127;
        const int cl = (tid >> 7) & 1;
        const int yh = tid >> 8;
        float* base = A + (cl * 64 + yh * 4) * RS + c;
        // d[x*4 + yr] = A[cl*64 + x*8 + yh*4 + yr][c]
#pragma unroll
        for (int x = 0; x < 8; x++)
#pragma unroll
            for (int yr = 0; yr < 4; yr++)
                d[x * 4 + yr] = base[(x * 8 + yr) * RS];
#pragma unroll
        for (int xo = 0; xo < 8; xo++) {
            const float4 ua = *(const float4*)(sU + 64 + xo * 8);
            const float4 ub = *(const float4*)(sU + 64 + xo * 8 + 4);
            // out row = cl*64 + xo*8 + yh*4 + yr (own row set)
            base[(xo * 8 + 0) * RS] = dot8s4(ua, ub, d);
            base[(xo * 8 + 1) * RS] = dot8s4(ua, ub, d + 1);
            base[(xo * 8 + 2) * RS] = dot8s4(ua, ub, d + 2);
            base[(xo * 8 + 3) * RS] = dot8s4(ua, ub, d + 3);
        }
    }
    __syncthreads();

    // ---- P4: fused channel expansion + coalesced store (2 items/thread) ----
    float wc[8];
#pragma unroll
    for (int i = 0; i < 8; i++) wc[i] = sU[128 + i];

    float4* outb = (float4*)(out + (long)b * 65536);
    const float4* Af = (const float4*)A;    // row stride RS/4 = 33

#pragma unroll
    for (int it = 0; it < 2; it++) {
        const int item = tid + it * NT;
        const int irv = item & 15;          // right pixel / 4
        const int il  = item >> 4;          // left pixel, 0..63

        const float4 m00 = Af[il * 33 + irv];
        const float4 m01 = Af[il * 33 + 16 + irv];
        const float4 m10 = Af[(64 + il) * 33 + irv];
        const float4 m11 = Af[(64 + il) * 33 + 16 + irv];

#pragma unroll
        for (int cpr = 0; cpr < 4; cpr++) {
            const float w0 = wc[cpr * 2], w1 = wc[cpr * 2 + 1];
            float4 t0, t1;
            t0.x = fmaf(w1, m01.x, w0 * m00.x);
            t0.y = fmaf(w1, m01.y, w0 * m00.y);
            t0.z = fmaf(w1, m01.z, w0 * m00.z);
            t0.w = fmaf(w1, m01.w, w0 * m00.w);
            t1.x = fmaf(w1, m11.x, w0 * m10.x);
            t1.y = fmaf(w1, m11.y, w0 * m10.y);
            t1.z = fmaf(w1, m11.z, w0 * m10.z);
            t1.w = fmaf(w1, m11.w, w0 * m10.w);
#pragma unroll
            for (int cpl = 0; cpl < 4; cpl++) {
                const float v0 = wc[cpl * 2], v1 = wc[cpl * 2 + 1];
                float4 o;
                o.x = fmaf(v1, t1.x, v0 * t0.x);
                o.y = fmaf(v1, t1.y, v0 * t0.y);
                o.z = fmaf(v1, t1.z, v0 * t0.z);
                o.w = fmaf(v1, t1.w, v0 * t0.w);
                outb[(cpl * 64 + il) * 64 + cpr * 16 + irv] = o;
            }
        }
    }
}

extern "C" void kernel_launch(void* const* d_in, const int* in_sizes, int n_in,
                              void* d_out, int out_size)
{
    const float* rho = (const float*)d_in[0];
    const float* ux  = (const float*)d_in[1];
    const float* uy  = (const float*)d_in[2];
    const float* uc  = (const float*)d_in[3];
    float* out = (float*)d_out;

    const int B = in_sizes[0] / 16384;

    cudaFuncSetAttribute(qconv_kernel,
                         cudaFuncAttributeMaxDynamicSharedMemorySize, SMEM_BYTES);
    qconv_kernel<<<B, NT, SMEM_BYTES>>>(rho, ux, uy, uc, out);
}

// round 7
// speedup vs baseline: 1.2153x; 1.2153x over previous
#include <cuda_runtime.h>

// QConv2d: new_rho[b] = U2 @ rho[b] @ U2^T, U2 = uc[:,2:4] ⊗ ux ⊗ uy
// Register-resident separable evaluation with the CTA split into TWO
// independent half-pipelines (rows/left-channel 0 vs 1), joined only at P4.
//
// smem tile A: 128 rows x 132 words (RS=132 -> stride-4/stride-1 patterns all
// conflict-free). Half H (threads H*128..H*128+127):
//   P1h: load rho rows [H*64, H*64+64) (coalesced float4)
//   barH
//   P2h: per-thread row-half (r in H-block) register transform
//   barH
//   P3h: per-thread column x cl=H register transform (in-place, own addrs)
// full __syncthreads
//   P4 : fused uc on both sides + coalesced float4 stores.

#define NT 256
#define RS 132
#define A_WORDS (128 * RS)            // 16896
#define SMEM_WORDS (A_WORDS + 2 * 136)
#define SMEM_BYTES (SMEM_WORDS * 4)

__device__ __forceinline__ void half_bar(int H) {
    asm volatile("bar.sync %0, 128;" :: "r"(H + 1) : "memory");
}

__device__ __forceinline__ void transform64(float* __restrict__ d,
                                            const float4* __restrict__ Uy4,
                                            const float4* __restrict__ Ux4)
{
    // uy pass: 8 contiguous groups (x fixed)
#pragma unroll
    for (int x = 0; x < 8; x++) {
        float v[8];
#pragma unroll
        for (int k = 0; k < 8; k++) v[k] = d[x * 8 + k];
#pragma unroll
        for (int yo = 0; yo < 8; yo++) {
            const float4 ua = Uy4[yo * 2], ub = Uy4[yo * 2 + 1];
            float a =      ua.x * v[0];
            a = fmaf(ua.y, v[1], a);
            a = fmaf(ua.z, v[2], a);
            a = fmaf(ua.w, v[3], a);
            a = fmaf(ub.x, v[4], a);
            a = fmaf(ub.y, v[5], a);
            a = fmaf(ub.z, v[6], a);
            a = fmaf(ub.w, v[7], a);
            d[x * 8 + yo] = a;
        }
    }
    // ux pass: stride-8 groups (y fixed)
#pragma unroll
    for (int y = 0; y < 8; y++) {
        float v[8];
#pragma unroll
        for (int k = 0; k < 8; k++) v[k] = d[k * 8 + y];
#pragma unroll
        for (int xo = 0; xo < 8; xo++) {
            const float4 ua = Ux4[xo * 2], ub = Ux4[xo * 2 + 1];
            float a =      ua.x * v[0];
            a = fmaf(ua.y, v[1], a);
            a = fmaf(ua.z, v[2], a);
            a = fmaf(ua.w, v[3], a);
            a = fmaf(ub.x, v[4], a);
            a = fmaf(ub.y, v[5], a);
            a = fmaf(ub.z, v[6], a);
            a = fmaf(ub.w, v[7], a);
            d[xo * 8 + y] = a;
        }
    }
}

__global__ __launch_bounds__(NT, 2)
void qconv_kernel(const float* __restrict__ rho,
                  const float* __restrict__ gux,
                  const float* __restrict__ guy,
                  const float* __restrict__ guc,
                  float* __restrict__ out)
{
    extern __shared__ float sm[];
    float* A = sm;                        // 128 x 132
    // per-half U copies so init stays inside the half-barrier domain
    // layout per half: [0:64) uy, [64:128) ux, [128:136) wc
    const int tid   = threadIdx.x;
    const int H     = tid >> 7;           // half id (also left-channel block)
    const int local = tid & 127;
    float* sU = sm + A_WORDS + H * 136;

    const int b = blockIdx.x;

    // ---- init U + wc (each half its own copy) ----
    if (local < 64) {
        sU[local] = guy[local];
    } else {
        sU[local] = gux[local - 64];
    }
    if (local < 8) {                      // i = c'*2 + c
        sU[128 + local] = guc[(local >> 1) * 4 + (local & 1) + 2];
    }

    // ---- P1 (half): load rho rows [H*64, H*64+64) coalesced ----
    {
        const float4* src = (const float4*)(rho + (long)b * 16384) + H * 2048;
#pragma unroll
        for (int i = 0; i < 16; i++) {
            const int idx = local + i * 128;        // float4 index within half
            const float4 v = src[idx];
            const int w = idx * 4;                  // word within half
            const int r = H * 64 + (w >> 7);
            const int c = w & 127;
            *(float4*)(A + r * RS + c) = v;
        }
    }
    half_bar(H);

    const float4* Uy4 = (const float4*)sU;
    const float4* Ux4 = (const float4*)(sU + 64);

    // ---- P2 (half): right-side transform, one row-half per thread ----
    {
        const int h = local >> 6;                   // right-channel half of the row
        const int r = H * 64 + (local & 63);        // row within this half's block
        float* base = A + r * RS + h * 64;
        float d[64];
#pragma unroll
        for (int i = 0; i < 16; i++) {
            const float4 v = *(const float4*)(base + 4 * i);
            d[4 * i] = v.x; d[4 * i + 1] = v.y; d[4 * i + 2] = v.z; d[4 * i + 3] = v.w;
        }
        transform64(d, Uy4, Ux4);
#pragma unroll
        for (int i = 0; i < 16; i++)
            *(float4*)(base + 4 * i) =
                make_float4(d[4 * i], d[4 * i + 1], d[4 * i + 2], d[4 * i + 3]);
    }
    half_bar(H);

    // ---- P3 (half): left-side transform, column x cl=H per thread ----
    // Each (row-block, column) is owned by exactly one thread; read-all then
    // write-all in registers -> no barrier inside.
    {
        const int c = local;
        float* base = A + (H * 64) * RS + c;
        float d[64];
#pragma unroll
        for (int i = 0; i < 64; i++) d[i] = base[i * RS];   // lanes stride-1
        transform64(d, Uy4, Ux4);
#pragma unroll
        for (int i = 0; i < 64; i++) base[i * RS] = d[i];
    }
    __syncthreads();

    // ---- P4: fused channel expansion on both sides + coalesced store ----
    float wc[8];
    {
        const float* wsrc = sm + A_WORDS + 128;     // half-0 copy (valid post-sync)
#pragma unroll
        for (int i = 0; i < 8; i++) wc[i] = wsrc[i];
    }

    float4* outb = (float4*)(out + (long)b * 65536);
    const float4* Af = (const float4*)A;            // row stride 33 float4

#pragma unroll
    for (int it = 0; it < 4; it++) {
        const int item = tid + it * NT;
        const int irv = item & 15;                  // right pixel / 4
        const int il  = item >> 4;                  // left pixel, 0..63

        const float4 m00 = Af[il * 33 + irv];              // cl=0, cr=0
        const float4 m01 = Af[il * 33 + 16 + irv];         // cl=0, cr=1
        const float4 m10 = Af[(64 + il) * 33 + irv];       // cl=1, cr=0
        const float4 m11 = Af[(64 + il) * 33 + 16 + irv];  // cl=1, cr=1

#pragma unroll
        for (int cpr = 0; cpr < 4; cpr++) {
            const float w0 = wc[cpr * 2], w1 = wc[cpr * 2 + 1];
            float4 t0, t1;
            t0.x = fmaf(w1, m01.x, w0 * m00.x);
            t0.y = fmaf(w1, m01.y, w0 * m00.y);
            t0.z = fmaf(w1, m01.z, w0 * m00.z);
            t0.w = fmaf(w1, m01.w, w0 * m00.w);
            t1.x = fmaf(w1, m11.x, w0 * m10.x);
            t1.y = fmaf(w1, m11.y, w0 * m10.y);
            t1.z = fmaf(w1, m11.z, w0 * m10.z);
            t1.w = fmaf(w1, m11.w, w0 * m10.w);
#pragma unroll
            for (int cpl = 0; cpl < 4; cpl++) {
                const float v0 = wc[cpl * 2], v1 = wc[cpl * 2 + 1];
                float4 o;
                o.x = fmaf(v1, t1.x, v0 * t0.x);
                o.y = fmaf(v1, t1.y, v0 * t0.y);
                o.z = fmaf(v1, t1.z, v0 * t0.z);
                o.w = fmaf(v1, t1.w, v0 * t0.w);
                outb[(cpl * 64 + il) * 64 + cpr * 16 + irv] = o;
            }
        }
    }
}

extern "C" void kernel_launch(void* const* d_in, const int* in_sizes, int n_in,
                              void* d_out, int out_size)
{
    const float* rho = (const float*)d_in[0];
    const float* ux  = (const float*)d_in[1];
    const float* uy  = (const float*)d_in[2];
    const float* uc  = (const float*)d_in[3];
    float* out = (float*)d_out;

    const int B = in_sizes[0] / 16384;

    cudaFuncSetAttribute(qconv_kernel,
                         cudaFuncAttributeMaxDynamicSharedMemorySize, SMEM_BYTES);
    qconv_kernel<<<B, NT, SMEM_BYTES>>>(rho, ux, uy, uc, out);
}